// round 2
// baseline (speedup 1.0000x reference)
#include <cuda_runtime.h>
#include <cstdint>

#define B_  32
#define W_  900
#define C_  256
#define WP  1024   // padded W (zero rows 900..1023)

// ---------------- device scratch (allowed: __device__ globals) ----------------
__device__ float g_xn1[B_][WP][C_];     // normalized, tf32-rounded input_1 (33.5MB)
__device__ float g_xn2[B_][WP][C_];     // normalized, tf32-rounded input_2
__device__ float g_invn[2][B_][C_];     // inverse L2 norms per (input,b,c)
__device__ float g_part[B_][8][W_];     // per-(b, m-tile) partial outputs

__device__ __forceinline__ float to_tf32(float x) {
    uint32_t u;
    asm("cvt.rna.tf32.f32 %0, %1;" : "=r"(u) : "f"(x));
    return __uint_as_float(u);
}

__device__ __forceinline__ void mma_tf32(float* d, const uint32_t* a, const uint32_t* b) {
    asm volatile(
        "mma.sync.aligned.m16n8k8.row.col.f32.tf32.tf32.f32 "
        "{%0,%1,%2,%3}, {%4,%5,%6,%7}, {%8,%9}, {%0,%1,%2,%3};\n"
        : "+f"(d[0]), "+f"(d[1]), "+f"(d[2]), "+f"(d[3])
        : "r"(a[0]), "r"(a[1]), "r"(a[2]), "r"(a[3]),
          "r"(b[0]), "r"(b[1]));
}

// ---------------- kernel 1: sum of squares over W per (input, b, c) ----------------
// grid 64 = (input, b); 256 threads: thread = (wsub 0..3, c4 0..63)
__global__ void k_norms(const float* __restrict__ x1, const float* __restrict__ x2) {
    const int inp = blockIdx.x & 1;
    const int b   = blockIdx.x >> 1;
    const float4* src = reinterpret_cast<const float4*>(inp ? x2 : x1);
    const int tid = threadIdx.x;
    const int c4 = tid & 63, ws = tid >> 6;

    float4 s = make_float4(0.f, 0.f, 0.f, 0.f);
    for (int k = 0; k < 225; k++) {
        const int w = ws + 4 * k;                 // covers 0..899
        float4 v = src[((size_t)b * W_ + w) * 64 + c4];
        s.x += v.x * v.x; s.y += v.y * v.y; s.z += v.z * v.z; s.w += v.w * v.w;
    }
    __shared__ float4 red[256];
    red[tid] = s;
    __syncthreads();
    if (tid < 64) {
        float4 a = red[tid], b4 = red[tid + 64], c = red[tid + 128], d = red[tid + 192];
        float r0 = a.x + b4.x + c.x + d.x;
        float r1 = a.y + b4.y + c.y + d.y;
        float r2 = a.z + b4.z + c.z + d.z;
        float r3 = a.w + b4.w + c.w + d.w;
        g_invn[inp][b][c4 * 4 + 0] = 1.f / sqrtf(fmaxf(r0, 1e-12f));
        g_invn[inp][b][c4 * 4 + 1] = 1.f / sqrtf(fmaxf(r1, 1e-12f));
        g_invn[inp][b][c4 * 4 + 2] = 1.f / sqrtf(fmaxf(r2, 1e-12f));
        g_invn[inp][b][c4 * 4 + 3] = 1.f / sqrtf(fmaxf(r3, 1e-12f));
    }
}

// ---------------- kernel 2: normalize + tf32 round + zero-pad to 1024 rows ----------
// grid 1024 = (input<<9 | b<<4 | wchunk); 256 threads; block covers 64 w-rows.
__global__ void k_normalize(const float* __restrict__ x1, const float* __restrict__ x2) {
    const int inp = blockIdx.x >> 9;
    const int b   = (blockIdx.x >> 4) & 31;
    const int wc  = blockIdx.x & 15;
    const int tid = threadIdx.x;
    const int c4  = tid & 63;

    const float4* src = reinterpret_cast<const float4*>(inp ? x2 : x1);
    float* dstbase = inp ? &g_xn2[b][0][0] : &g_xn1[b][0][0];
    const float4 n = reinterpret_cast<const float4*>(&g_invn[inp][b][0])[c4];

#pragma unroll
    for (int p = 0; p < 16; p++) {
        const int w = wc * 64 + p * 4 + (tid >> 6);
        float4 o;
        if (w < W_) {
            float4 v = src[((size_t)b * W_ + w) * 64 + c4];
            o.x = to_tf32(v.x * n.x);
            o.y = to_tf32(v.y * n.y);
            o.z = to_tf32(v.z * n.z);
            o.w = to_tf32(v.w * n.w);
        } else {
            o = make_float4(0.f, 0.f, 0.f, 0.f);
        }
        reinterpret_cast<float4*>(dstbase)[(size_t)w * 64 + c4] = o;
    }
}

// ---------------- kernel 3: main GEMM + anti-diagonal epilogue ----------------
// One block per (b, mt): mt = m-tile of 128 rows of x1n (padded to 1024).
// smem: sA[128][260] (full K=256, resident), sB[128][68] (k-chunk 64) overlaid
// with sG[128][132] (tile result), jacc[900] bins.
#define SA_S 260
#define SB_S 68
#define SG_S 132
#define SMEM_FLOATS (128 * SA_S + 128 * SG_S + 904)

__global__ __launch_bounds__(256, 1) void k_corr() {
    extern __shared__ float sm[];
    float* sA   = sm;                          // 128*260
    float* sB   = sm + 128 * SA_S;             // 128*68   (overlaid with sG)
    float* sG   = sB;                          // 128*132
    float* jacc = sm + 128 * SA_S + 128 * SG_S; // 900 (+pad)

    const int b   = blockIdx.x >> 3;
    const int mt  = blockIdx.x & 7;
    const int tid = threadIdx.x;

    for (int idx = tid; idx < W_; idx += 256) jacc[idx] = 0.f;

    // load A tile: rows mt*128..+127, full K=256 (each row = 64 float4, contiguous)
    const float4* gA = reinterpret_cast<const float4*>(&g_xn1[b][mt * 128][0]);
#pragma unroll
    for (int p = 0; p < 32; p++) {
        const int idx = p * 256 + tid;         // 0..8191
        const int row = idx >> 6, c4 = idx & 63;
        *reinterpret_cast<float4*>(&sA[row * SA_S + c4 * 4]) = gA[idx];
    }

    const int lane = tid & 31, wid = tid >> 5;
    const int gid = lane >> 2, tig = lane & 3;
    const int wm = wid >> 2, wn = wid & 3;     // 2x4 warp grid -> 64x32 per warp

#pragma unroll 1
    for (int it = 0; it < 8; it++) {
        float acc[4][4][4];
#pragma unroll
        for (int mf = 0; mf < 4; mf++)
#pragma unroll
            for (int nf = 0; nf < 4; nf++)
#pragma unroll
                for (int r = 0; r < 4; r++) acc[mf][nf][r] = 0.f;

        const float4* gB = reinterpret_cast<const float4*>(&g_xn2[b][it * 128][0]);

#pragma unroll 1
        for (int ch = 0; ch < 4; ch++) {       // K chunks of 64
            __syncthreads();                   // protect sB/sG reuse
#pragma unroll
            for (int p = 0; p < 8; p++) {
                const int idx = p * 256 + tid; // 0..2047
                const int row = idx >> 4, c4 = idx & 15;
                *reinterpret_cast<float4*>(&sB[row * SB_S + c4 * 4]) =
                    gB[row * 64 + ch * 16 + c4];
            }
            __syncthreads();

#pragma unroll
            for (int ks = 0; ks < 8; ks++) {   // k-steps of 8
                const int kb = ch * 64 + ks * 8;
                uint32_t af[4][4];
#pragma unroll
                for (int mf = 0; mf < 4; mf++) {
                    const float* pa = &sA[(wm * 64 + mf * 16 + gid) * SA_S + kb + tig];
                    af[mf][0] = __float_as_uint(pa[0]);
                    af[mf][1] = __float_as_uint(pa[8 * SA_S]);
                    af[mf][2] = __float_as_uint(pa[4]);
                    af[mf][3] = __float_as_uint(pa[8 * SA_S + 4]);
                }
                uint32_t bfr[4][2];
#pragma unroll
                for (int nf = 0; nf < 4; nf++) {
                    const float* pb = &sB[(wn * 32 + nf * 8 + gid) * SB_S + ks * 8 + tig];
                    bfr[nf][0] = __float_as_uint(pb[0]);
                    bfr[nf][1] = __float_as_uint(pb[4]);
                }
#pragma unroll
                for (int mf = 0; mf < 4; mf++)
#pragma unroll
                    for (int nf = 0; nf < 4; nf++)
                        mma_tf32(acc[mf][nf], af[mf], bfr[nf]);
            }
        }

        // epilogue: tile -> smem, then per-anti-diagonal sums (no atomics)
        __syncthreads();
#pragma unroll
        for (int mf = 0; mf < 4; mf++)
#pragma unroll
            for (int nf = 0; nf < 4; nf++) {
                const int row = wm * 64 + mf * 16 + gid;
                const int col = wn * 32 + nf * 8 + tig * 2;
                *reinterpret_cast<float2*>(&sG[row * SG_S + col]) =
                    make_float2(acc[mf][nf][0], acc[mf][nf][1]);
                *reinterpret_cast<float2*>(&sG[(row + 8) * SG_S + col]) =
                    make_float2(acc[mf][nf][2], acc[mf][nf][3]);
            }
        __syncthreads();

        if (tid < 255) {
            const int d = tid - 127;           // m_loc - i_loc
            const int mlo = d > 0 ? d : 0;
            const int mhi = d < 0 ? d + 127 : 127;
            float s = 0.f;
            for (int m = mlo; m <= mhi; m++) s += sG[m * SG_S + (m - d)];
            // j = (m_glob - i_glob - 450) mod 900; +1800 bias keeps it positive
            int t = 128 * (mt - it) + tid + 1223;   // in [327, 2373]
            if (t >= 1800) t -= 1800;
            if (t >= 900)  t -= 900;
            jacc[t] += s;                      // unique bin per thread per tile
        }
        // next iteration's leading __syncthreads orders sG overwrite & jacc
    }

    __syncthreads();
    for (int idx = tid; idx < W_; idx += 256)
        g_part[b][mt][idx] = jacc[idx];
}

// ---------------- kernel 4: combine m-tile partials ----------------
__global__ void k_combine(float* __restrict__ out) {
    const int b = blockIdx.x, j = threadIdx.x;
    if (j < W_) {
        float s = 0.f;
#pragma unroll
        for (int mtv = 0; mtv < 8; mtv++) s += g_part[b][mtv][j];
        out[b * W_ + j] = s;
    }
}

// ---------------- launch ----------------
extern "C" void kernel_launch(void* const* d_in, const int* in_sizes, int n_in,
                              void* d_out, int out_size) {
    (void)in_sizes; (void)n_in; (void)out_size;
    const float* x1 = (const float*)d_in[0];
    const float* x2 = (const float*)d_in[1];

    cudaFuncSetAttribute(k_corr, cudaFuncAttributeMaxDynamicSharedMemorySize,
                         SMEM_FLOATS * 4);

    k_norms<<<64, 256>>>(x1, x2);
    k_normalize<<<1024, 256>>>(x1, x2);
    k_corr<<<256, 256, SMEM_FLOATS * 4>>>();
    k_combine<<<32, 900>>>((float*)d_out);
}

// round 3
// speedup vs baseline: 1.3863x; 1.3863x over previous
#include <cuda_runtime.h>
#include <cstdint>

#define B_  32
#define W_  900
#define C_  256

// ---------------- device scratch ----------------
__device__ float g_invn[2][B_][C_];     // inverse L2 norms per (input,b,c)
__device__ float g_part[B_][8][W_];     // per-(b, m-tile) partial outputs

__device__ __forceinline__ float to_tf32(float x) {
    uint32_t u;
    asm("cvt.rna.tf32.f32 %0, %1;" : "=r"(u) : "f"(x));
    return __uint_as_float(u);
}

__device__ __forceinline__ void mma_tf32(float* d, const uint32_t* a, const uint32_t* b) {
    asm volatile(
        "mma.sync.aligned.m16n8k8.row.col.f32.tf32.tf32.f32 "
        "{%0,%1,%2,%3}, {%4,%5,%6,%7}, {%8,%9}, {%0,%1,%2,%3};\n"
        : "+f"(d[0]), "+f"(d[1]), "+f"(d[2]), "+f"(d[3])
        : "r"(a[0]), "r"(a[1]), "r"(a[2]), "r"(a[3]),
          "r"(b[0]), "r"(b[1]));
}

__device__ __forceinline__ void cp_async16(uint32_t saddr, const void* gptr, int src_bytes) {
    asm volatile("cp.async.cg.shared.global [%0], [%1], 16, %2;"
                 :: "r"(saddr), "l"(gptr), "r"(src_bytes));
}
__device__ __forceinline__ void cp_commit() {
    asm volatile("cp.async.commit_group;");
}
__device__ __forceinline__ void cp_wait0() {
    asm volatile("cp.async.wait_group 0;");
}

// ---------------- kernel 1: sum of squares over W per (input, b, c) ----------------
__global__ void k_norms(const float* __restrict__ x1, const float* __restrict__ x2) {
    const int inp = blockIdx.x & 1;
    const int b   = blockIdx.x >> 1;
    const float4* src = reinterpret_cast<const float4*>(inp ? x2 : x1);
    const int tid = threadIdx.x;
    const int c4 = tid & 63, ws = tid >> 6;

    float4 s = make_float4(0.f, 0.f, 0.f, 0.f);
    for (int k = 0; k < 225; k++) {
        const int w = ws + 4 * k;
        float4 v = src[((size_t)b * W_ + w) * 64 + c4];
        s.x += v.x * v.x; s.y += v.y * v.y; s.z += v.z * v.z; s.w += v.w * v.w;
    }
    __shared__ float4 red[256];
    red[tid] = s;
    __syncthreads();
    if (tid < 64) {
        float4 a = red[tid], b4 = red[tid + 64], c = red[tid + 128], d = red[tid + 192];
        float r0 = a.x + b4.x + c.x + d.x;
        float r1 = a.y + b4.y + c.y + d.y;
        float r2 = a.z + b4.z + c.z + d.z;
        float r3 = a.w + b4.w + c.w + d.w;
        g_invn[inp][b][c4 * 4 + 0] = 1.f / sqrtf(fmaxf(r0, 1e-12f));
        g_invn[inp][b][c4 * 4 + 1] = 1.f / sqrtf(fmaxf(r1, 1e-12f));
        g_invn[inp][b][c4 * 4 + 2] = 1.f / sqrtf(fmaxf(r2, 1e-12f));
        g_invn[inp][b][c4 * 4 + 3] = 1.f / sqrtf(fmaxf(r3, 1e-12f));
    }
}

// ---------------- kernel 2: GEMM + anti-diagonal epilogue ----------------
// Both norms folded into A (A' = x1 * s1[c]*s2[c], rna->tf32). B = raw x2 via
// cp.async zfill (HW-truncated to tf32 by the mma). B double-buffered; sG
// overlays the two B buffers.
#define SA_S 260
#define SB_S 68
#define SG_S 132
#define OFF_BUF   (128 * SA_S)                  // 33280
#define OFF_JACC  (OFF_BUF + 2 * 128 * SB_S)    // 50688
#define OFF_SCALE (OFF_JACC + 904)              // 51592
#define SMEM_FLOATS (OFF_SCALE + 256)           // 51848 -> 207392 B

__global__ __launch_bounds__(256, 1) void k_corr(const float* __restrict__ x1,
                                                 const float* __restrict__ x2) {
    extern __shared__ float sm[];
    float* sA     = sm;
    float* sG     = sm + OFF_BUF;              // overlays both B buffers
    float* jacc   = sm + OFF_JACC;
    float* sScale = sm + OFF_SCALE;

    const int b   = blockIdx.x >> 3;
    const int mt  = blockIdx.x & 7;
    const int tid = threadIdx.x;

    for (int idx = tid; idx < W_; idx += 256) jacc[idx] = 0.f;
    sScale[tid] = g_invn[0][b][tid] * g_invn[1][b][tid];   // 256 threads = 256 c
    __syncthreads();

    // A tile: rows mt*128..+127 of x1, scaled by combined norm, rna->tf32
    const float4* gA = reinterpret_cast<const float4*>(x1) + (size_t)b * W_ * 64;
    const float4* sSc4 = reinterpret_cast<const float4*>(sScale);
#pragma unroll
    for (int p = 0; p < 32; p++) {
        const int idx = p * 256 + tid;         // 0..8191
        const int row = idx >> 6, c4 = idx & 63;
        const int m = mt * 128 + row;
        float4 o = make_float4(0.f, 0.f, 0.f, 0.f);
        if (m < W_) {
            float4 v = gA[(size_t)m * 64 + c4];
            float4 s = sSc4[c4];
            o.x = to_tf32(v.x * s.x);
            o.y = to_tf32(v.y * s.y);
            o.z = to_tf32(v.z * s.z);
            o.w = to_tf32(v.w * s.w);
        }
        *reinterpret_cast<float4*>(&sA[row * SA_S + c4 * 4]) = o;
    }

    const int lane = tid & 31, wid = tid >> 5;
    const int gid = lane >> 2, tig = lane & 3;
    const int wm = wid >> 2, wn = wid & 3;     // 2x4 warp grid -> 64x32 per warp

    const float* gB = x2 + (size_t)b * W_ * C_;
    const uint32_t smBuf = (uint32_t)__cvta_generic_to_shared(sm + OFF_BUF);

    // per-thread B-load coordinates: idx = p*256+tid -> row=idx>>4, c4f=idx&15
#pragma unroll 1
    for (int it = 0; it < 8; it++) {
        float acc[4][4][4];
#pragma unroll
        for (int mf = 0; mf < 4; mf++)
#pragma unroll
            for (int nf = 0; nf < 4; nf++)
#pragma unroll
                for (int r = 0; r < 4; r++) acc[mf][nf][r] = 0.f;

        // issue chunk 0 -> buf0
        {
#pragma unroll
            for (int p = 0; p < 8; p++) {
                const int idx = p * 256 + tid;
                const int row = idx >> 4, c4f = idx & 15;
                const int i_g = it * 128 + row;
                const bool ok = i_g < W_;
                const float* g = gB + (ok ? ((size_t)i_g * C_ + c4f * 4) : 0);
                cp_async16(smBuf + (row * SB_S + c4f * 4) * 4, g, ok ? 16 : 0);
            }
            cp_commit();
        }

#pragma unroll 1
        for (int ch = 0; ch < 4; ch++) {
            cp_wait0();
            __syncthreads();
            if (ch < 3) {                      // prefetch next chunk into other buffer
                const uint32_t dst = smBuf + (((ch + 1) & 1) ? 128 * SB_S * 4 : 0);
#pragma unroll
                for (int p = 0; p < 8; p++) {
                    const int idx = p * 256 + tid;
                    const int row = idx >> 4, c4f = idx & 15;
                    const int i_g = it * 128 + row;
                    const bool ok = i_g < W_;
                    const float* g = gB + (ok ? ((size_t)i_g * C_ + (ch + 1) * 64 + c4f * 4) : 0);
                    cp_async16(dst + (row * SB_S + c4f * 4) * 4, g, ok ? 16 : 0);
                }
                cp_commit();
            }
            const float* sB = sm + OFF_BUF + ((ch & 1) ? 128 * SB_S : 0);

#pragma unroll
            for (int ks = 0; ks < 8; ks++) {
                const int kb = ch * 64 + ks * 8;
                uint32_t af[4][4];
#pragma unroll
                for (int mf = 0; mf < 4; mf++) {
                    const float* pa = &sA[(wm * 64 + mf * 16 + gid) * SA_S + kb + tig];
                    af[mf][0] = __float_as_uint(pa[0]);
                    af[mf][1] = __float_as_uint(pa[8 * SA_S]);
                    af[mf][2] = __float_as_uint(pa[4]);
                    af[mf][3] = __float_as_uint(pa[8 * SA_S + 4]);
                }
                uint32_t bfr[4][2];
#pragma unroll
                for (int nf = 0; nf < 4; nf++) {
                    const float* pb = &sB[(wn * 32 + nf * 8 + gid) * SB_S + ks * 8 + tig];
                    bfr[nf][0] = __float_as_uint(pb[0]);
                    bfr[nf][1] = __float_as_uint(pb[4]);
                }
#pragma unroll
                for (int mf = 0; mf < 4; mf++)
#pragma unroll
                    for (int nf = 0; nf < 4; nf++)
                        mma_tf32(acc[mf][nf], af[mf], bfr[nf]);
            }
        }

        // epilogue: acc -> sG (overwrites B buffers), then anti-diagonal sums
        __syncthreads();
#pragma unroll
        for (int mf = 0; mf < 4; mf++)
#pragma unroll
            for (int nf = 0; nf < 4; nf++) {
                const int row = wm * 64 + mf * 16 + gid;
                const int col = wn * 32 + nf * 8 + tig * 2;
                *reinterpret_cast<float2*>(&sG[row * SG_S + col]) =
                    make_float2(acc[mf][nf][0], acc[mf][nf][1]);
                *reinterpret_cast<float2*>(&sG[(row + 8) * SG_S + col]) =
                    make_float2(acc[mf][nf][2], acc[mf][nf][3]);
            }
        __syncthreads();

        if (tid < 255) {
            const int d = tid - 127;           // m_loc - i_loc
            const int mlo = d > 0 ? d : 0;
            const int mhi = d < 0 ? d + 127 : 127;
            float s = 0.f;
            for (int m = mlo; m <= mhi; m++) s += sG[m * SG_S + (m - d)];
            int t = 128 * (mt - it) + tid + 1223;   // (m-i-450) mod 900, biased
            if (t >= 1800) t -= 1800;
            if (t >= 900)  t -= 900;
            jacc[t] += s;
        }
        __syncthreads();                       // sG/jacc done before next it's cp.async
    }

    for (int idx = tid; idx < W_; idx += 256)
        g_part[b][mt][idx] = jacc[idx];
}

// ---------------- dummy: shifts ncu -s 5 -c 1 capture onto k_corr ----------------
__global__ void k_dummy() {}

// ---------------- kernel 3: combine m-tile partials ----------------
__global__ void k_combine(float* __restrict__ out) {
    const int b = blockIdx.x, j = threadIdx.x;
    if (j < W_) {
        float s = 0.f;
#pragma unroll
        for (int mtv = 0; mtv < 8; mtv++) s += g_part[b][mtv][j];
        out[b * W_ + j] = s;
    }
}

// ---------------- launch ----------------
extern "C" void kernel_launch(void* const* d_in, const int* in_sizes, int n_in,
                              void* d_out, int out_size) {
    (void)in_sizes; (void)n_in; (void)out_size;
    const float* x1 = (const float*)d_in[0];
    const float* x2 = (const float*)d_in[1];

    cudaFuncSetAttribute(k_corr, cudaFuncAttributeMaxDynamicSharedMemorySize,
                         SMEM_FLOATS * 4);

    k_norms<<<64, 256>>>(x1, x2);
    k_corr<<<256, 256, SMEM_FLOATS * 4>>>(x1, x2);
    k_dummy<<<1, 32>>>();
    k_combine<<<32, 900>>>((float*)d_out);
}

// round 4
// speedup vs baseline: 1.4098x; 1.0169x over previous
#include <cuda_runtime.h>
#include <cstdint>

#define B_  32
#define W_  900
#define C_  256

// ---------------- device scratch ----------------
__device__ float g_npart[2][B_][8][C_];   // per-(input,b,wslice,c) partial sumsq
__device__ float g_invn[2][B_][C_];       // inverse L2 norms per (input,b,c)
__device__ float g_part[B_][8][W_];       // per-(b, m-tile) partial outputs

__device__ __forceinline__ float to_tf32(float x) {
    uint32_t u;
    asm("cvt.rna.tf32.f32 %0, %1;" : "=r"(u) : "f"(x));
    return __uint_as_float(u);
}

__device__ __forceinline__ void mma_tf32(float* d, const uint32_t* a, const uint32_t* b) {
    asm volatile(
        "mma.sync.aligned.m16n8k8.row.col.f32.tf32.tf32.f32 "
        "{%0,%1,%2,%3}, {%4,%5,%6,%7}, {%8,%9}, {%0,%1,%2,%3};\n"
        : "+f"(d[0]), "+f"(d[1]), "+f"(d[2]), "+f"(d[3])
        : "r"(a[0]), "r"(a[1]), "r"(a[2]), "r"(a[3]),
          "r"(b[0]), "r"(b[1]));
}

__device__ __forceinline__ void cp_async16(uint32_t saddr, const void* gptr, int src_bytes) {
    asm volatile("cp.async.cg.shared.global [%0], [%1], 16, %2;"
                 :: "r"(saddr), "l"(gptr), "r"(src_bytes));
}
__device__ __forceinline__ void cp_commit() { asm volatile("cp.async.commit_group;"); }
__device__ __forceinline__ void cp_wait0()  { asm volatile("cp.async.wait_group 0;"); }

// ---------------- kernel 1a: partial sum-of-squares (512 blocks) ----------------
// grid 512 = (inp<<8 | b<<3 | slice); slice covers 113 rows (last: 109)
__global__ void k_norms1(const float* __restrict__ x1, const float* __restrict__ x2) {
    const int inp = blockIdx.x >> 8;
    const int b   = (blockIdx.x >> 3) & 31;
    const int sl  = blockIdx.x & 7;
    const float4* src = reinterpret_cast<const float4*>(inp ? x2 : x1);
    const int tid = threadIdx.x;
    const int c4 = tid & 63, ws = tid >> 6;

    const int w0 = sl * 113;
    const int wend = (sl == 7) ? W_ : (w0 + 113);

    float4 s = make_float4(0.f, 0.f, 0.f, 0.f);
#pragma unroll 4
    for (int w = w0 + ws; w < wend; w += 4) {
        float4 v = src[((size_t)b * W_ + w) * 64 + c4];
        s.x += v.x * v.x; s.y += v.y * v.y; s.z += v.z * v.z; s.w += v.w * v.w;
    }
    __shared__ float4 red[256];
    red[tid] = s;
    __syncthreads();
    if (tid < 64) {
        float4 a = red[tid], b4 = red[tid + 64], c = red[tid + 128], d = red[tid + 192];
        float4 r;
        r.x = a.x + b4.x + c.x + d.x;
        r.y = a.y + b4.y + c.y + d.y;
        r.z = a.z + b4.z + c.z + d.z;
        r.w = a.w + b4.w + c.w + d.w;
        reinterpret_cast<float4*>(&g_npart[inp][b][sl][0])[c4] = r;
    }
}

// ---------------- kernel 1b: combine partials -> inverse norms ----------------
__global__ void k_norms2() {
    const int inp = blockIdx.x & 1;
    const int b   = blockIdx.x >> 1;
    const int c   = threadIdx.x;
    float s = 0.f;
#pragma unroll
    for (int sl = 0; sl < 8; sl++) s += g_npart[inp][b][sl][c];
    g_invn[inp][b][c] = 1.f / sqrtf(fmaxf(s, 1e-12f));
}

// ---------------- kernel 2: GEMM + anti-diagonal epilogue ----------------
// Block tile 128(M)x128(N), K chunked by 32, A and B double-buffered cp.async.
// Norm scale folded into B register fragments. 78KB smem -> 2 blocks/SM.
#define SAB_S 36
#define SG_S  132
#define BUFSZ (128 * SAB_S)                 // 4608 floats per buffer
#define OFF_B    (2 * BUFSZ)                // 9216
#define OFF_JACC (4 * BUFSZ)                // 18432 (sG overlays [0, 16896))
#define OFF_SCALE (OFF_JACC + 904)          // 19336
#define SMEM_FLOATS (OFF_SCALE + 256)       // 19592 floats = 78368 B

__global__ __launch_bounds__(256, 2) void k_corr(const float* __restrict__ x1,
                                                 const float* __restrict__ x2) {
    extern __shared__ float sm[];
    float* sG     = sm;                     // overlays all 4 A/B buffers
    float* jacc   = sm + OFF_JACC;
    float* sScale = sm + OFF_SCALE;

    const int b   = blockIdx.x >> 3;
    const int mt  = blockIdx.x & 7;
    const int tid = threadIdx.x;

    for (int idx = tid; idx < W_; idx += 256) jacc[idx] = 0.f;
    sScale[tid] = g_invn[0][b][tid] * g_invn[1][b][tid];
    __syncthreads();

    const float* gA = x1 + (size_t)b * W_ * C_;
    const float* gB = x2 + (size_t)b * W_ * C_;
    const uint32_t sbase = (uint32_t)__cvta_generic_to_shared(sm);

    const int lrow = tid >> 3;              // 0..31 (row group base)
    const int lc4  = tid & 7;               // float4 index within 32-float chunk

    const int lane = tid & 31, wid = tid >> 5;
    const int gid = lane >> 2, tig = lane & 3;
    const int wm = wid >> 2, wn = wid & 3;  // 2x4 warp grid -> 64x32 per warp

#pragma unroll 1
    for (int it = 0; it < 8; it++) {
        float acc[4][4][4];
#pragma unroll
        for (int mf = 0; mf < 4; mf++)
#pragma unroll
            for (int nf = 0; nf < 4; nf++)
#pragma unroll
                for (int r = 0; r < 4; r++) acc[mf][nf][r] = 0.f;

        // issue chunk 0 into buffer 0
        {
#pragma unroll
            for (int p = 0; p < 4; p++) {
                const int row = lrow + p * 32;
                const int m = mt * 128 + row;
                const bool okA = m < W_;
                cp_async16(sbase + (row * SAB_S + lc4 * 4) * 4,
                           gA + (okA ? ((size_t)m * C_ + lc4 * 4) : 0), okA ? 16 : 0);
                const int ig = it * 128 + row;
                const bool okB = ig < W_;
                cp_async16(sbase + (OFF_B + row * SAB_S + lc4 * 4) * 4,
                           gB + (okB ? ((size_t)ig * C_ + lc4 * 4) : 0), okB ? 16 : 0);
            }
            cp_commit();
        }

#pragma unroll 1
        for (int ch = 0; ch < 8; ch++) {    // 8 K-chunks of 32
            cp_wait0();
            __syncthreads();
            if (ch < 7) {                   // prefetch next chunk into other buffer
                const uint32_t aoff = ((ch + 1) & 1) ? BUFSZ : 0;
#pragma unroll
                for (int p = 0; p < 4; p++) {
                    const int row = lrow + p * 32;
                    const int m = mt * 128 + row;
                    const bool okA = m < W_;
                    cp_async16(sbase + (aoff + row * SAB_S + lc4 * 4) * 4,
                               gA + (okA ? ((size_t)m * C_ + (ch + 1) * 32 + lc4 * 4) : 0),
                               okA ? 16 : 0);
                    const int ig = it * 128 + row;
                    const bool okB = ig < W_;
                    cp_async16(sbase + (OFF_B + aoff + row * SAB_S + lc4 * 4) * 4,
                               gB + (okB ? ((size_t)ig * C_ + (ch + 1) * 32 + lc4 * 4) : 0),
                               okB ? 16 : 0);
                }
                cp_commit();
            }
            const float* sA = sm + ((ch & 1) ? BUFSZ : 0);
            const float* sB = sm + OFF_B + ((ch & 1) ? BUFSZ : 0);

#pragma unroll
            for (int ks = 0; ks < 4; ks++) {       // 4 k-steps of 8 per chunk
                const int klo = ks * 8 + tig;      // local k of frag lane
                const float s0 = sScale[ch * 32 + klo];
                const float s1 = sScale[ch * 32 + klo + 4];
                uint32_t af[4][4];
#pragma unroll
                for (int mf = 0; mf < 4; mf++) {
                    const float* pa = &sA[(wm * 64 + mf * 16 + gid) * SAB_S + klo];
                    af[mf][0] = __float_as_uint(pa[0]);
                    af[mf][1] = __float_as_uint(pa[8 * SAB_S]);
                    af[mf][2] = __float_as_uint(pa[4]);
                    af[mf][3] = __float_as_uint(pa[8 * SAB_S + 4]);
                }
                uint32_t bfr[4][2];
#pragma unroll
                for (int nf = 0; nf < 4; nf++) {
                    const float* pb = &sB[(wn * 32 + nf * 8 + gid) * SAB_S + klo];
                    bfr[nf][0] = __float_as_uint(to_tf32(pb[0] * s0));
                    bfr[nf][1] = __float_as_uint(to_tf32(pb[4] * s1));
                }
#pragma unroll
                for (int mf = 0; mf < 4; mf++)
#pragma unroll
                    for (int nf = 0; nf < 4; nf++)
                        mma_tf32(acc[mf][nf], af[mf], bfr[nf]);
            }
        }

        // epilogue: acc -> sG (overwrites A/B buffers), then anti-diagonal sums
        __syncthreads();
#pragma unroll
        for (int mf = 0; mf < 4; mf++)
#pragma unroll
            for (int nf = 0; nf < 4; nf++) {
                const int row = wm * 64 + mf * 16 + gid;
                const int col = wn * 32 + nf * 8 + tig * 2;
                *reinterpret_cast<float2*>(&sG[row * SG_S + col]) =
                    make_float2(acc[mf][nf][0], acc[mf][nf][1]);
                *reinterpret_cast<float2*>(&sG[(row + 8) * SG_S + col]) =
                    make_float2(acc[mf][nf][2], acc[mf][nf][3]);
            }
        __syncthreads();

        if (tid < 255) {
            const int d = tid - 127;        // m_loc - i_loc
            const int mlo = d > 0 ? d : 0;
            const int mhi = d < 0 ? d + 127 : 127;
            float s = 0.f;
            for (int m = mlo; m <= mhi; m++) s += sG[m * SG_S + (m - d)];
            int t = 128 * (mt - it) + tid + 1223;   // (m-i-450) mod 900, biased
            if (t >= 1800) t -= 1800;
            if (t >= 900)  t -= 900;
            jacc[t] += s;
        }
        __syncthreads();                    // sG reads done before next it's cp.async
    }

    for (int idx = tid; idx < W_; idx += 256)
        g_part[b][mt][idx] = jacc[idx];
}

// ---------------- dummy: aligns ncu capture (index 3) onto k_corr -------------
__global__ void k_dummy() {}

// ---------------- kernel 3: combine m-tile partials ----------------
__global__ void k_combine(float* __restrict__ out) {
    const int b = blockIdx.x, j = threadIdx.x;
    if (j < W_) {
        float s = 0.f;
#pragma unroll
        for (int mtv = 0; mtv < 8; mtv++) s += g_part[b][mtv][j];
        out[b * W_ + j] = s;
    }
}

// ---------------- launch ----------------
extern "C" void kernel_launch(void* const* d_in, const int* in_sizes, int n_in,
                              void* d_out, int out_size) {
    (void)in_sizes; (void)n_in; (void)out_size;
    const float* x1 = (const float*)d_in[0];
    const float* x2 = (const float*)d_in[1];

    cudaFuncSetAttribute(k_corr, cudaFuncAttributeMaxDynamicSharedMemorySize,
                         SMEM_FLOATS * 4);

    k_norms1<<<512, 256>>>(x1, x2);                     // idx 0
    k_norms2<<<64, 256>>>();                            // idx 1
    k_dummy<<<1, 32>>>();                               // idx 2
    k_corr<<<256, 256, SMEM_FLOATS * 4>>>(x1, x2);      // idx 3  <- ncu target
    k_combine<<<32, 900>>>((float*)d_out);              // idx 4
}

// round 7
// speedup vs baseline: 1.5910x; 1.1285x over previous
#include <cuda_runtime.h>
#include <cuda_fp16.h>
#include <cstdint>

#define B_  32
#define W_  900
#define C_  256

// ---------------- device scratch ----------------
__device__ float g_npart[2][B_][8][C_];               // partial sumsq
__device__ float g_invn[2][B_][C_];                   // inverse L2 norms
// staged fp16, layout [inp][b][tile][kc 8][row 128][40], chunk=5120 halfs
__device__ __align__(128) __half g_sh[2ull * B_ * 8 * 8 * 128 * 40];
__device__ float g_part[B_][8][W_];                   // per-(b,mt) partials

// ---------------- helpers ----------------
__device__ __forceinline__ uint32_t smem_u32(const void* p) {
    uint32_t a;
    asm("{ .reg .u64 t; cvta.to.shared.u64 t, %1; cvt.u32.u64 %0, t; }" : "=r"(a) : "l"(p));
    return a;
}
__device__ __forceinline__ void bulk_g2s(uint32_t dst, const void* src, uint32_t bytes,
                                         uint32_t mbar) {
    asm volatile("cp.async.bulk.shared::cta.global.mbarrier::complete_tx::bytes "
                 "[%0], [%1], %2, [%3];"
                 :: "r"(dst), "l"(src), "r"(bytes), "r"(mbar) : "memory");
}
#define MB_INIT(a, n) asm volatile("mbarrier.init.shared.b64 [%0], %1;" \
    :: "r"((uint32_t)(a)), "r"((uint32_t)(n)) : "memory")
#define MB_EXPECT_TX(a, n) asm volatile("mbarrier.arrive.expect_tx.shared.b64 _, [%0], %1;" \
    :: "r"((uint32_t)(a)), "r"((uint32_t)(n)) : "memory")
#define MB_WAIT(a, ph) do { \
    uint32_t _m = (uint32_t)(a), _p = (uint32_t)(ph), _d; \
    asm volatile("{\n\t.reg .pred p;\n\t" \
        "mbarrier.try_wait.parity.acquire.cta.shared::cta.b64 p, [%1], %2;\n\t" \
        "selp.b32 %0, 1, 0, p;\n\t}" : "=r"(_d) : "r"(_m), "r"(_p) : "memory"); \
    if (!_d) { \
        asm volatile("{\n\t.reg .pred P1;\n\t" \
            "W_%=:\n\t" \
            "mbarrier.try_wait.parity.acquire.cta.shared::cta.b64 P1, [%0], %1, 0x989680;\n\t" \
            "@P1 bra.uni D_%=;\n\t" \
            "bra.uni W_%=;\n\t" \
            "D_%=:\n\t}" :: "r"(_m), "r"(_p) : "memory"); \
    } } while (0)

#define LDMX4(r0, r1, r2, r3, addr) asm volatile( \
    "ldmatrix.sync.aligned.m8n8.x4.shared.b16 {%0,%1,%2,%3}, [%4];" \
    : "=r"(r0), "=r"(r1), "=r"(r2), "=r"(r3) : "r"(addr))

__device__ __forceinline__ void mma16816(float* d, const uint32_t* a, const uint32_t* b) {
    asm volatile(
        "mma.sync.aligned.m16n8k16.row.col.f32.f16.f16.f32 "
        "{%0,%1,%2,%3}, {%4,%5,%6,%7}, {%8,%9}, {%0,%1,%2,%3};\n"
        : "+f"(d[0]), "+f"(d[1]), "+f"(d[2]), "+f"(d[3])
        : "r"(a[0]), "r"(a[1]), "r"(a[2]), "r"(a[3]), "r"(b[0]), "r"(b[1]));
}

// ---------------- kernel 1a: partial sum-of-squares ----------------
__global__ void k_norms1(const float* __restrict__ x1, const float* __restrict__ x2) {
    const int inp = blockIdx.x >> 8;
    const int b   = (blockIdx.x >> 3) & 31;
    const int sl  = blockIdx.x & 7;
    const float4* src = reinterpret_cast<const float4*>(inp ? x2 : x1);
    const int tid = threadIdx.x;
    const int c4 = tid & 63, ws = tid >> 6;
    const int w0 = sl * 113;
    const int wend = (sl == 7) ? W_ : (w0 + 113);

    float4 s = make_float4(0.f, 0.f, 0.f, 0.f);
#pragma unroll 4
    for (int w = w0 + ws; w < wend; w += 4) {
        float4 v = src[((size_t)b * W_ + w) * 64 + c4];
        s.x += v.x * v.x; s.y += v.y * v.y; s.z += v.z * v.z; s.w += v.w * v.w;
    }
    __shared__ float4 red[256];
    red[tid] = s;
    __syncthreads();
    if (tid < 64) {
        float4 a = red[tid], b4 = red[tid + 64], c = red[tid + 128], d = red[tid + 192];
        float4 r;
        r.x = a.x + b4.x + c.x + d.x;
        r.y = a.y + b4.y + c.y + d.y;
        r.z = a.z + b4.z + c.z + d.z;
        r.w = a.w + b4.w + c.w + d.w;
        reinterpret_cast<float4*>(&g_npart[inp][b][sl][0])[c4] = r;
    }
}

// ---------------- kernel 1b: combine -> inverse norms ----------------
__global__ void k_norms2() {
    const int inp = blockIdx.x & 1;
    const int b   = blockIdx.x >> 1;
    const int c   = threadIdx.x;
    float s = 0.f;
#pragma unroll
    for (int sl = 0; sl < 8; sl++) s += g_npart[inp][b][sl][c];
    g_invn[inp][b][c] = 1.f / sqrtf(fmaxf(s, 1e-12f));
}

// ---------------- kernel 2: stage fp16 chunks (both inputs) ----------------
// grid 512 = (inp<<8 | b<<3 | tile). val = x * sqrt(s1[c]*s2[c]) -> half2.
__global__ __launch_bounds__(256) void k_stage(const float* __restrict__ x1,
                                               const float* __restrict__ x2) {
    __shared__ float h[256];
    const int inp  = blockIdx.x >> 8;
    const int b    = (blockIdx.x >> 3) & 31;
    const int tile = blockIdx.x & 7;
    const int tid  = threadIdx.x;
    h[tid] = sqrtf(g_invn[0][b][tid] * g_invn[1][b][tid]);
    __syncthreads();

    const float2* src = reinterpret_cast<const float2*>(inp ? x2 : x1)
                      + (size_t)b * W_ * 128;
    __half* dst = g_sh + ((size_t)inp * 256 + b * 8 + tile) * 40960;

#pragma unroll 4
    for (int p = 0; p < 64; p++) {             // 16384 half2 = 128 rows x 128 cpairs
        const int idx = p * 256 + tid;
        const int row = idx >> 7, cp = idx & 127;
        const int w = tile * 128 + row;
        const int c = cp * 2;
        __half2 v2 = __float2half2_rn(0.f);
        if (w < W_) {
            float2 v = src[(size_t)w * 128 + cp];
            v2 = __floats2half2_rn(v.x * h[c], v.y * h[c + 1]);
        }
        const int kc = c >> 5, kl = c & 31;
        *reinterpret_cast<__half2*>(dst + kc * 5120 + row * 40 + kl) = v2;
    }
    // pad columns 32..39 of every row/chunk -> zero
#pragma unroll
    for (int p = 0; p < 16; p++) {             // 4096 half2
        const int idx = p * 256 + tid;
        const int row = idx >> 5, kc = (idx >> 2) & 7, q = idx & 3;
        *reinterpret_cast<__half2*>(dst + kc * 5120 + row * 40 + 32 + q * 2) =
            __float2half2_rn(0.f);
    }
}

// ---------------- kernel 3: fp16 GEMM (bulk loads) + anti-diag epilogue ------
// smem: ctrl[0,1024) | A resident[1024, 82944) | B ring 2x10240 [82944,103424)
//       sG 128x132 f32 [103424,171008) | jacc [171008,174624)
#define SM_A    1024
#define SM_BR   82944
#define SM_SG   103424
#define SM_JACC 171008
#define SM_BYTES 174624
#define SG_S 132

__global__ __launch_bounds__(256, 1) void k_corr() {
    extern __shared__ float smf[];
    const uint32_t sbase = smem_u32(smf);
    const int tid = threadIdx.x, lane = tid & 31, wid = tid >> 5;
    const int gid = lane >> 2, tig = lane & 3;
    const int wm = wid >> 2, wn = wid & 3;      // 2x4 warps -> 64x32 tiles
    const int b = blockIdx.x >> 3, mt = blockIdx.x & 7;

    if (tid == 0) {
        MB_INIT(sbase + 0, 1);
        MB_INIT(sbase + 16, 1);
        MB_INIT(sbase + 32, 1);
    }
    __syncthreads();

    const __half* srcA = g_sh + ((size_t)b * 8 + mt) * 40960;          // inp 0
    const __half* srcB = g_sh + ((size_t)256 + b * 8) * 40960;         // inp 1, it0
    if (tid == 0) {
        MB_EXPECT_TX(sbase + 0, 81920);
        bulk_g2s(sbase + SM_A, srcA, 81920u, sbase + 0);
        MB_EXPECT_TX(sbase + 16, 10240);
        bulk_g2s(sbase + SM_BR, srcB, 10240u, sbase + 16);
    }

    float* sG   = smf + (SM_SG >> 2);
    float* jacc = smf + (SM_JACC >> 2);
    for (int i = tid; i < W_; i += 256) jacc[i] = 0.f;

    // per-thread ldmatrix byte offsets (within a 10240B chunk)
    int aoff[4], boff[2];
#pragma unroll
    for (int mf = 0; mf < 4; mf++)
        aoff[mf] = (wm * 64 + mf * 16 + (lane & 15)) * 80 + (lane >> 4) * 16;
#pragma unroll
    for (int np = 0; np < 2; np++)
        boff[np] = (wn * 32 + np * 16 + (lane >> 4) * 8 + (lane & 7)) * 80
                 + ((lane >> 3) & 1) * 16;

    MB_WAIT(sbase + 0, 0);       // A resident ready
    __syncthreads();             // jacc zeroed, everyone ready

    float acc[4][4][4];

#pragma unroll 1
    for (int g = 0; g < 64; g++) {
        const int s = g & 1;
        if (tid == 0 && g < 63) {
            MB_EXPECT_TX(sbase + 16 + (s ^ 1) * 16, 10240);
            bulk_g2s(sbase + SM_BR + (s ^ 1) * 10240,
                     srcB + (size_t)(g + 1) * 5120, 10240u,
                     sbase + 16 + (s ^ 1) * 16);
        }
        MB_WAIT(sbase + 16 + s * 16, (g >> 1) & 1);

        if ((g & 7) == 0) {
#pragma unroll
            for (int mf = 0; mf < 4; mf++)
#pragma unroll
                for (int nf = 0; nf < 4; nf++)
#pragma unroll
                    for (int r = 0; r < 4; r++) acc[mf][nf][r] = 0.f;
        }

        const uint32_t abase = sbase + SM_A + (g & 7) * 10240;
        const uint32_t bbase = sbase + SM_BR + s * 10240;

#pragma unroll
        for (int ks = 0; ks < 2; ks++) {
            uint32_t af[4][4], bf[2][4];
#pragma unroll
            for (int mf = 0; mf < 4; mf++)
                LDMX4(af[mf][0], af[mf][1], af[mf][2], af[mf][3],
                      abase + aoff[mf] + ks * 32);
#pragma unroll
            for (int np = 0; np < 2; np++)
                LDMX4(bf[np][0], bf[np][1], bf[np][2], bf[np][3],
                      bbase + boff[np] + ks * 32);
#pragma unroll
            for (int mf = 0; mf < 4; mf++)
#pragma unroll
                for (int nf = 0; nf < 4; nf++)
                    mma16816(acc[mf][nf], af[mf], &bf[nf >> 1][(nf & 1) * 2]);
        }

        if ((g & 7) == 7) {
            const int it = g >> 3;
            __syncthreads();     // all warps done with B stage + prior sG use
#pragma unroll
            for (int mf = 0; mf < 4; mf++)
#pragma unroll
                for (int nf = 0; nf < 4; nf++) {
                    const int row = wm * 64 + mf * 16 + gid;
                    const int col = wn * 32 + nf * 8 + tig * 2;
                    *reinterpret_cast<float2*>(&sG[row * SG_S + col]) =
                        make_float2(acc[mf][nf][0], acc[mf][nf][1]);
                    *reinterpret_cast<float2*>(&sG[(row + 8) * SG_S + col]) =
                        make_float2(acc[mf][nf][2], acc[mf][nf][3]);
                }
            __syncthreads();
            if (tid < 255) {
                const int d = tid - 127;          // m_loc - i_loc
                const int mlo = d > 0 ? d : 0;
                const int mhi = d < 0 ? d + 127 : 127;
                float sAcc = 0.f;
                for (int m = mlo; m <= mhi; m++) sAcc += sG[m * SG_S + (m - d)];
                int t = 128 * (mt - it) + tid + 1223;   // (m-i-450) mod 900
                if (t >= 1800) t -= 1800;
                if (t >= 900)  t -= 900;
                jacc[t] += sAcc;
            }
            __syncthreads();
        } else {
            __syncthreads();     // mark B stage consumed before reissue
        }
    }

    for (int i = tid; i < W_; i += 256) g_part[b][mt][i] = jacc[i];
}

// ---------------- kernel 4: combine m-tile partials ----------------
__global__ void k_combine(float* __restrict__ out) {
    const int b = blockIdx.x, j = threadIdx.x;
    if (j < W_) {
        float s = 0.f;
#pragma unroll
        for (int mtv = 0; mtv < 8; mtv++) s += g_part[b][mtv][j];
        out[b * W_ + j] = s;
    }
}

// ---------------- launch ----------------
extern "C" void kernel_launch(void* const* d_in, const int* in_sizes, int n_in,
                              void* d_out, int out_size) {
    (void)in_sizes; (void)n_in; (void)out_size;
    const float* x1 = (const float*)d_in[0];
    const float* x2 = (const float*)d_in[1];

    cudaFuncSetAttribute(k_corr, cudaFuncAttributeMaxDynamicSharedMemorySize, SM_BYTES);

    k_norms1<<<512, 256>>>(x1, x2);          // idx 0
    k_norms2<<<64, 256>>>();                 // idx 1
    k_stage<<<512, 256>>>(x1, x2);           // idx 2
    k_corr<<<256, 256, SM_BYTES>>>();        // idx 3  <- ncu captures this
    k_combine<<<32, 900>>>((float*)d_out);   // idx 4
}

// round 8
// speedup vs baseline: 1.9071x; 1.1986x over previous
#include <cuda_runtime.h>
#include <cuda_fp16.h>
#include <cstdint>

#define B_  32
#define W_  900
#define C_  256

// ---------------- device scratch ----------------
__device__ float g_npart[2][B_][8][C_];               // partial sumsq
__device__ float g_invn[2][B_][C_];                   // inverse L2 norms
// staged fp16, layout [inp][b][tile128][kc 8][row 128][40], chunk=5120 halfs
__device__ __align__(128) __half g_sh[2ull * B_ * 8 * 8 * 128 * 40];
__device__ float g_part[B_][16][W_];                  // per-(b,mt64) partials

// ---------------- helpers ----------------
__device__ __forceinline__ uint32_t smem_u32(const void* p) {
    uint32_t a;
    asm("{ .reg .u64 t; cvta.to.shared.u64 t, %1; cvt.u32.u64 %0, t; }" : "=r"(a) : "l"(p));
    return a;
}
__device__ __forceinline__ void bulk_g2s(uint32_t dst, const void* src, uint32_t bytes,
                                         uint32_t mbar) {
    asm volatile("cp.async.bulk.shared::cta.global.mbarrier::complete_tx::bytes "
                 "[%0], [%1], %2, [%3];"
                 :: "r"(dst), "l"(src), "r"(bytes), "r"(mbar) : "memory");
}
#define MB_INIT(a, n) asm volatile("mbarrier.init.shared.b64 [%0], %1;" \
    :: "r"((uint32_t)(a)), "r"((uint32_t)(n)) : "memory")
#define MB_EXPECT_TX(a, n) asm volatile("mbarrier.arrive.expect_tx.shared.b64 _, [%0], %1;" \
    :: "r"((uint32_t)(a)), "r"((uint32_t)(n)) : "memory")
#define MB_WAIT(a, ph) do { \
    uint32_t _m = (uint32_t)(a), _p = (uint32_t)(ph), _d; \
    asm volatile("{\n\t.reg .pred p;\n\t" \
        "mbarrier.try_wait.parity.acquire.cta.shared::cta.b64 p, [%1], %2;\n\t" \
        "selp.b32 %0, 1, 0, p;\n\t}" : "=r"(_d) : "r"(_m), "r"(_p) : "memory"); \
    if (!_d) { \
        asm volatile("{\n\t.reg .pred P1;\n\t" \
            "W_%=:\n\t" \
            "mbarrier.try_wait.parity.acquire.cta.shared::cta.b64 P1, [%0], %1, 0x989680;\n\t" \
            "@P1 bra.uni D_%=;\n\t" \
            "bra.uni W_%=;\n\t" \
            "D_%=:\n\t}" :: "r"(_m), "r"(_p) : "memory"); \
    } } while (0)

#define LDMX4(r0, r1, r2, r3, addr) asm volatile( \
    "ldmatrix.sync.aligned.m8n8.x4.shared.b16 {%0,%1,%2,%3}, [%4];" \
    : "=r"(r0), "=r"(r1), "=r"(r2), "=r"(r3) : "r"(addr))

__device__ __forceinline__ void mma16816(float* d, const uint32_t* a, const uint32_t* b) {
    asm volatile(
        "mma.sync.aligned.m16n8k16.row.col.f32.f16.f16.f32 "
        "{%0,%1,%2,%3}, {%4,%5,%6,%7}, {%8,%9}, {%0,%1,%2,%3};\n"
        : "+f"(d[0]), "+f"(d[1]), "+f"(d[2]), "+f"(d[3])
        : "r"(a[0]), "r"(a[1]), "r"(a[2]), "r"(a[3]), "r"(b[0]), "r"(b[1]));
}

// ---------------- kernel 1a: partial sum-of-squares ----------------
__global__ void k_norms1(const float* __restrict__ x1, const float* __restrict__ x2) {
    const int inp = blockIdx.x >> 8;
    const int b   = (blockIdx.x >> 3) & 31;
    const int sl  = blockIdx.x & 7;
    const float4* src = reinterpret_cast<const float4*>(inp ? x2 : x1);
    const int tid = threadIdx.x;
    const int c4 = tid & 63, ws = tid >> 6;
    const int w0 = sl * 113;
    const int wend = (sl == 7) ? W_ : (w0 + 113);

    float4 s = make_float4(0.f, 0.f, 0.f, 0.f);
#pragma unroll 4
    for (int w = w0 + ws; w < wend; w += 4) {
        float4 v = src[((size_t)b * W_ + w) * 64 + c4];
        s.x += v.x * v.x; s.y += v.y * v.y; s.z += v.z * v.z; s.w += v.w * v.w;
    }
    __shared__ float4 red[256];
    red[tid] = s;
    __syncthreads();
    if (tid < 64) {
        float4 a = red[tid], b4 = red[tid + 64], c = red[tid + 128], d = red[tid + 192];
        float4 r;
        r.x = a.x + b4.x + c.x + d.x;
        r.y = a.y + b4.y + c.y + d.y;
        r.z = a.z + b4.z + c.z + d.z;
        r.w = a.w + b4.w + c.w + d.w;
        reinterpret_cast<float4*>(&g_npart[inp][b][sl][0])[c4] = r;
    }
}

// ---------------- kernel 1b: combine -> inverse norms ----------------
__global__ void k_norms2() {
    const int inp = blockIdx.x & 1;
    const int b   = blockIdx.x >> 1;
    const int c   = threadIdx.x;
    float s = 0.f;
#pragma unroll
    for (int sl = 0; sl < 8; sl++) s += g_npart[inp][b][sl][c];
    g_invn[inp][b][c] = 1.f / sqrtf(fmaxf(s, 1e-12f));
}

// ---------------- kernel 2: stage fp16 chunks (both inputs) ----------------
__global__ __launch_bounds__(256) void k_stage(const float* __restrict__ x1,
                                               const float* __restrict__ x2) {
    __shared__ float h[256];
    const int inp  = blockIdx.x >> 8;
    const int b    = (blockIdx.x >> 3) & 31;
    const int tile = blockIdx.x & 7;
    const int tid  = threadIdx.x;
    h[tid] = sqrtf(g_invn[0][b][tid] * g_invn[1][b][tid]);
    __syncthreads();

    const float2* src = reinterpret_cast<const float2*>(inp ? x2 : x1)
                      + (size_t)b * W_ * 128;
    __half* dst = g_sh + ((size_t)inp * 256 + b * 8 + tile) * 40960;

#pragma unroll 4
    for (int p = 0; p < 64; p++) {             // 16384 half2 = 128 rows x 128 cpairs
        const int idx = p * 256 + tid;
        const int row = idx >> 7, cp = idx & 127;
        const int w = tile * 128 + row;
        const int c = cp * 2;
        __half2 v2 = __float2half2_rn(0.f);
        if (w < W_) {
            float2 v = src[(size_t)w * 128 + cp];
            v2 = __floats2half2_rn(v.x * h[c], v.y * h[c + 1]);
        }
        const int kc = c >> 5, kl = c & 31;
        *reinterpret_cast<__half2*>(dst + kc * 5120 + row * 40 + kl) = v2;
    }
#pragma unroll
    for (int p = 0; p < 16; p++) {             // pad cols 32..39 -> zero
        const int idx = p * 256 + tid;
        const int row = idx >> 5, kc = (idx >> 2) & 7, q = idx & 3;
        *reinterpret_cast<__half2*>(dst + kc * 5120 + row * 40 + 32 + q * 2) =
            __float2half2_rn(0.f);
    }
}

// ---------------- kernel 3: fp16 GEMM 64x128 tiles, 2 blocks/SM ----------------
// smem: ctrl[0,1024) | A[1024,41984) 8x5120 | ring 3x10240 [41984,72704)
//       sG 64x132 f32 [72704,106496) | jacc [106496,110112)
#define SM_A    1024
#define SM_BR   41984
#define SM_SG   72704
#define SM_JACC 106496
#define SM_BYTES 110112
#define SG_S 132

__global__ __launch_bounds__(256, 2) void k_corr() {
    extern __shared__ float smf[];
    const uint32_t sbase = smem_u32(smf);
    const int tid = threadIdx.x, lane = tid & 31, wid = tid >> 5;
    const int gid = lane >> 2, tig = lane & 3;
    const int wm = wid >> 2, wn = wid & 3;      // 2x4 warps -> 32x32 tiles
    const int b = blockIdx.x >> 4, mt = blockIdx.x & 15;   // 64-row m-tiles

    if (tid == 0) {
        MB_INIT(sbase + 0, 1);                  // A
        MB_INIT(sbase + 16, 1);                 // B stage 0
        MB_INIT(sbase + 32, 1);                 // B stage 1
        MB_INIT(sbase + 48, 1);                 // B stage 2
    }
    __syncthreads();

    // A: 8 half-chunk slices (64 rows) of staged 128-row tile mt>>1
    const __half* srcA = g_sh + ((size_t)b * 8 + (mt >> 1)) * 40960 + (mt & 1) * 2560;
    const __half* srcB = g_sh + ((size_t)256 + b * 8) * 40960;
    if (tid == 0) {
        MB_EXPECT_TX(sbase + 0, 40960);
#pragma unroll
        for (int kc = 0; kc < 8; kc++)
            bulk_g2s(sbase + SM_A + kc * 5120, srcA + (size_t)kc * 5120, 5120u, sbase + 0);
        // pre-issue B chunks 0..2
#pragma unroll
        for (int s = 0; s < 3; s++) {
            MB_EXPECT_TX(sbase + 16 + s * 16, 10240);
            bulk_g2s(sbase + SM_BR + s * 10240, srcB + (size_t)s * 5120, 10240u,
                     sbase + 16 + s * 16);
        }
    }

    float* sG   = smf + (SM_SG >> 2);
    float* jacc = smf + (SM_JACC >> 2);
    for (int i = tid; i < W_; i += 256) jacc[i] = 0.f;

    // ldmatrix byte offsets (A within 5120B chunk, B within 10240B chunk)
    int aoff[2], boff[2];
#pragma unroll
    for (int mf = 0; mf < 2; mf++)
        aoff[mf] = (wm * 32 + mf * 16 + (lane & 15)) * 80 + (lane >> 4) * 16;
#pragma unroll
    for (int np = 0; np < 2; np++)
        boff[np] = (wn * 32 + np * 16 + (lane >> 4) * 8 + (lane & 7)) * 80
                 + ((lane >> 3) & 1) * 16;

    MB_WAIT(sbase + 0, 0);       // A resident
    __syncthreads();             // jacc zeroed

    float acc[2][4][4];

#pragma unroll 1
    for (int g = 0; g < 64; g++) {
        const int s = g % 3;
        MB_WAIT(sbase + 16 + s * 16, (g / 3) & 1);

        if ((g & 7) == 0) {
#pragma unroll
            for (int mf = 0; mf < 2; mf++)
#pragma unroll
                for (int nf = 0; nf < 4; nf++)
#pragma unroll
                    for (int r = 0; r < 4; r++) acc[mf][nf][r] = 0.f;
        }

        const uint32_t abase = sbase + SM_A + (g & 7) * 5120;
        const uint32_t bbase = sbase + SM_BR + s * 10240;

#pragma unroll
        for (int ks = 0; ks < 2; ks++) {
            uint32_t af[2][4], bf[2][4];
#pragma unroll
            for (int mf = 0; mf < 2; mf++)
                LDMX4(af[mf][0], af[mf][1], af[mf][2], af[mf][3],
                      abase + aoff[mf] + ks * 32);
#pragma unroll
            for (int np = 0; np < 2; np++)
                LDMX4(bf[np][0], bf[np][1], bf[np][2], bf[np][3],
                      bbase + boff[np] + ks * 32);
#pragma unroll
            for (int mf = 0; mf < 2; mf++)
#pragma unroll
                for (int nf = 0; nf < 4; nf++)
                    mma16816(acc[mf][nf], af[mf], &bf[nf >> 1][(nf & 1) * 2]);
        }

        if ((g & 7) == 7) {
            const int it = g >> 3;
            __syncthreads();     // prior sG/diag use complete
#pragma unroll
            for (int mf = 0; mf < 2; mf++)
#pragma unroll
                for (int nf = 0; nf < 4; nf++) {
                    const int row = wm * 32 + mf * 16 + gid;
                    const int col = wn * 32 + nf * 8 + tig * 2;
                    *reinterpret_cast<float2*>(&sG[row * SG_S + col]) =
                        make_float2(acc[mf][nf][0], acc[mf][nf][1]);
                    *reinterpret_cast<float2*>(&sG[(row + 8) * SG_S + col]) =
                        make_float2(acc[mf][nf][2], acc[mf][nf][3]);
                }
            __syncthreads();
            if (tid < 191) {
                const int d = tid - 127;          // m_loc - i_loc, [-127, 63]
                const int mlo = d > 0 ? d : 0;
                const int mhi = (d + 127 < 63) ? d + 127 : 63;
                float sAcc = 0.f;
                for (int m = mlo; m <= mhi; m++) sAcc += sG[m * SG_S + (m - d)];
                int t = 64 * mt - 128 * it + tid + 1223;   // (m-i-450) mod 900
                if (t >= 1800) t -= 1800;
                if (t >= 900)  t -= 900;
                jacc[t] += sAcc;
            }
        }

        __syncthreads();         // stage s consumed (and epilogue done)
        if (tid == 0 && g + 3 < 64) {
            MB_EXPECT_TX(sbase + 16 + s * 16, 10240);
            bulk_g2s(sbase + SM_BR + s * 10240, srcB + (size_t)(g + 3) * 5120,
                     10240u, sbase + 16 + s * 16);
        }
    }

    for (int i = tid; i < W_; i += 256) g_part[b][mt][i] = jacc[i];
}

// ---------------- kernel 4: combine m-tile partials ----------------
__global__ void k_combine(float* __restrict__ out) {
    const int b = blockIdx.x, j = threadIdx.x;
    if (j < W_) {
        float s = 0.f;
#pragma unroll
        for (int mtv = 0; mtv < 16; mtv++) s += g_part[b][mtv][j];
        out[b * W_ + j] = s;
    }
}

// ---------------- launch ----------------
extern "C" void kernel_launch(void* const* d_in, const int* in_sizes, int n_in,
                              void* d_out, int out_size) {
    (void)in_sizes; (void)n_in; (void)out_size;
    const float* x1 = (const float*)d_in[0];
    const float* x2 = (const float*)d_in[1];

    cudaFuncSetAttribute(k_corr, cudaFuncAttributeMaxDynamicSharedMemorySize, SM_BYTES);

    k_norms1<<<512, 256>>>(x1, x2);          // idx 0
    k_norms2<<<64, 256>>>();                 // idx 1
    k_stage<<<512, 256>>>(x1, x2);           // idx 2
    k_corr<<<512, 256, SM_BYTES>>>();        // idx 3  <- ncu captures this
    k_combine<<<32, 900>>>((float*)d_out);   // idx 4
}